// round 1
// baseline (speedup 1.0000x reference)
#include <cuda_runtime.h>
#include <math.h>

// Problem constants
#define BV 64
#define NV 20
#define KV 10
#define TV 128
#define LV 40
#define EV 64
#define NKV 200          // N*k
#define G4 256           // 4*E
#define SUPROWS (BV*NKV) // 12800
#define TGTROWS (BV*TV)  // 8192
#define KITERS 5

// Scratch (device globals; no allocation allowed)
__device__ float g_sup_enc[SUPROWS*EV];
__device__ float g_tgt_enc[TGTROWS*EV];
__device__ float g_pre_gf[SUPROWS*G4];
__device__ float g_pre_gb[SUPROWS*G4];
__device__ float g_hf[SUPROWS*EV];
__device__ float g_hb[SUPROWS*EV];
__device__ float g_pre_x[TGTROWS*G4];

__device__ __forceinline__ float sigf(float x) { return 1.0f / (1.0f + __expf(-x)); }
__device__ __forceinline__ float tanhfast(float x) {
    float a = fabsf(x);
    float t = __expf(-2.0f * a);
    float r = (1.0f - t) / (1.0f + t);
    return copysignf(r, x);
}

// ---------------------------------------------------------------------------
// Kernel 1: embedding gather-sums for support and target rows.
// 64 threads per row (thread = embedding dim), 4 rows per 256-thread block.
// ---------------------------------------------------------------------------
__global__ __launch_bounds__(256) void embed_sum_kernel(
    const int* __restrict__ sup_tok,
    const int* __restrict__ tgt_tok,
    const float* __restrict__ emb)
{
    int row = blockIdx.x * 4 + (threadIdx.x >> 6);
    int e = threadIdx.x & 63;
    const int* tok;
    float* out;
    if (row < SUPROWS) {
        tok = sup_tok + row * LV;
        out = g_sup_enc + row * EV;
    } else {
        int r2 = row - SUPROWS;
        if (r2 >= TGTROWS) return;
        tok = tgt_tok + r2 * LV;
        out = g_tgt_enc + r2 * EV;
    }
    float acc = 0.0f;
#pragma unroll 8
    for (int l = 0; l < LV; l++) {
        int t = tok[l];
        acc += emb[t * EV + e];
    }
    out[e] = acc;
}

// ---------------------------------------------------------------------------
// Kernel 2: C[M,256] = A[M,64] @ W[256,64]^T + (b1 + b2)
// Block: 64 rows x 256 cols, 256 threads, 8x8 register tile per thread.
// ---------------------------------------------------------------------------
__global__ __launch_bounds__(256) void gemm_pre_kernel(
    const float* __restrict__ A, const float* __restrict__ W,
    const float* __restrict__ b1, const float* __restrict__ b2,
    float* __restrict__ C)
{
    __shared__ float A_sh[64][64];
    __shared__ float Wt_sh[64][256];   // transposed: Wt[e][j] = W[j][e]
    __shared__ float bias_sh[256];

    int tid = threadIdx.x;
    int tx = tid & 31, ty = tid >> 5;
    int row0 = blockIdx.x * 64;

    for (int idx = tid; idx < 256 * 64; idx += 256) {
        int j = idx >> 6, e = idx & 63;
        Wt_sh[e][j] = W[idx];
    }
    bias_sh[tid] = b1[tid] + b2[tid];
    for (int idx = tid; idx < 64 * 64; idx += 256) {
        A_sh[idx >> 6][idx & 63] = A[row0 * 64 + idx];
    }
    __syncthreads();

    float acc[8][8];
#pragma unroll
    for (int i = 0; i < 8; i++)
#pragma unroll
        for (int q = 0; q < 8; q++) acc[i][q] = 0.0f;

    for (int e = 0; e < 64; e++) {
        float a[8], bb[8];
#pragma unroll
        for (int i = 0; i < 8; i++) a[i] = A_sh[ty * 8 + i][e];
#pragma unroll
        for (int q = 0; q < 8; q++) bb[q] = Wt_sh[e][tx + 32 * q];
#pragma unroll
        for (int i = 0; i < 8; i++)
#pragma unroll
            for (int q = 0; q < 8; q++) acc[i][q] = fmaf(a[i], bb[q], acc[i][q]);
    }

#pragma unroll
    for (int i = 0; i < 8; i++) {
        int r = row0 + ty * 8 + i;
#pragma unroll
        for (int q = 0; q < 8; q++) {
            int j = tx + 32 * q;
            C[r * 256 + j] = acc[i][q] + bias_sh[j];
        }
    }
}

// ---------------------------------------------------------------------------
// Kernel 3: bidirectional LSTM over the 200-step support sequence.
// One block per (batch, direction): 128 blocks, 256 threads.
// Thread j holds Whh row j in registers; h broadcast from SMEM.
// ---------------------------------------------------------------------------
__global__ __launch_bounds__(256) void lstm_kernel(
    const float* __restrict__ gf_Whh, const float* __restrict__ gb_Whh)
{
    int bx = blockIdx.x;
    int dir = bx & 1, b = bx >> 1;
    int tid = threadIdx.x;
    const float* Whh = dir ? gb_Whh : gf_Whh;
    const float* pre = dir ? g_pre_gb : g_pre_gf;
    float* out = dir ? g_hb : g_hf;

    float w[64];
#pragma unroll
    for (int e = 0; e < 64; e++) w[e] = Whh[tid * 64 + e];

    __shared__ __align__(16) float h_sh[64];
    __shared__ float z_sh[256];
    if (tid < 64) h_sh[tid] = 0.0f;
    float c = 0.0f;
    __syncthreads();

    for (int s = 0; s < NKV; s++) {
        int srow = dir ? (NKV - 1 - s) : s;
        int row = b * NKV + srow;
        float z = pre[row * 256 + tid];
        const float4* h4 = (const float4*)h_sh;
#pragma unroll
        for (int q = 0; q < 16; q++) {
            float4 hv = h4[q];
            z = fmaf(hv.x, w[4 * q + 0], z);
            z = fmaf(hv.y, w[4 * q + 1], z);
            z = fmaf(hv.z, w[4 * q + 2], z);
            z = fmaf(hv.w, w[4 * q + 3], z);
        }
        z_sh[tid] = z;
        __syncthreads();
        if (tid < 64) {
            float zi = z_sh[tid], zf = z_sh[64 + tid];
            float zg = z_sh[128 + tid], zo = z_sh[192 + tid];
            c = sigf(zf) * c + sigf(zi) * tanhfast(zg);
            float h = sigf(zo) * tanhfast(c);
            h_sh[tid] = h;
            out[row * 64 + tid] = h;
        }
        __syncthreads();
    }
}

// ---------------------------------------------------------------------------
// Kernel 4: fused K-hop attention + final cosine softmax.
// grid 128: block = (b, half of T). 256 threads; each warp owns 8 target rows.
// sup_emb (200x64) and f_Whh (256x64) resident in dynamic SMEM (padded).
// Per-lane register states: x, r, c for e = lane and lane+32.
// Gate layout trick: z column j = lane + 32q -> all 4 gates of output e land
// in the same lane, so cell activations never leave registers.
// ---------------------------------------------------------------------------
__global__ __launch_bounds__(256) void attn_kernel(
    const float* __restrict__ f_Whh, float* __restrict__ out)
{
    extern __shared__ float sm[];
    float* S   = sm;                      // [200][65]
    float* WH  = S + 200 * 65;            // [256][65]
    float* H   = WH + 256 * 65;           // [64][64]
    float* ATT = H + 64 * 64;             // [64][200]
    float* SN  = ATT + 64 * 200;          // [200]

    int tid = threadIdx.x;
    int L = tid & 31, w = tid >> 5;
    int b = blockIdx.x >> 1, half = blockIdx.x & 1;
    int srow0 = b * NKV;
    int trow0 = b * TV + half * 64;       // global target-row base for this block

    // Load sup_emb = hf + hb + sup_enc
    for (int idx = tid; idx < NKV * 64; idx += 256) {
        int n = idx >> 6, e = idx & 63;
        int gr = (srow0 + n) * 64 + e;
        S[n * 65 + e] = g_hf[gr] + g_hb[gr] + g_sup_enc[gr];
    }
    // Load f_Whh
    for (int idx = tid; idx < 256 * 64; idx += 256) {
        int j = idx >> 6, e = idx & 63;
        WH[j * 65 + e] = f_Whh[idx];
    }
    for (int idx = tid; idx < 64 * 64; idx += 256) H[idx] = 0.0f;

    // Per-lane register state for this warp's 8 rows
    float x0[8], x1[8], r0[8], r1[8], c0[8], c1[8];
#pragma unroll
    for (int i = 0; i < 8; i++) {
        int grow = trow0 + w * 8 + i;
        x0[i] = g_tgt_enc[grow * 64 + L];
        x1[i] = g_tgt_enc[grow * 64 + 32 + L];
        r0[i] = r1[i] = c0[i] = c1[i] = 0.0f;
    }
    __syncthreads();

    int n6 = 192 + (L & 7);  // lanes >= 8 compute a duplicate (discarded)

    for (int iter = 0; iter < KITERS; iter++) {
        // h = h + r
#pragma unroll
        for (int i = 0; i < 8; i++) {
            int tl = w * 8 + i;
            H[tl * 64 + L]      += r0[i];
            H[tl * 64 + 32 + L] += r1[i];
        }
        __syncwarp();

        if (iter < KITERS - 1) {
            // scores[t][n] = H[t] . S[n]  (lane covers n = L + 32q)
            float sc[8][7];
#pragma unroll
            for (int i = 0; i < 8; i++)
#pragma unroll
                for (int q = 0; q < 7; q++) sc[i][q] = 0.0f;

            for (int e = 0; e < 64; e++) {
                float a[8];
#pragma unroll
                for (int i = 0; i < 8; i++) a[i] = H[(w * 8 + i) * 64 + e];
#pragma unroll
                for (int q = 0; q < 6; q++) {
                    float bv = S[(L + 32 * q) * 65 + e];
#pragma unroll
                    for (int i = 0; i < 8; i++) sc[i][q] = fmaf(a[i], bv, sc[i][q]);
                }
                float bv6 = S[n6 * 65 + e];
#pragma unroll
                for (int i = 0; i < 8; i++) sc[i][6] = fmaf(a[i], bv6, sc[i][6]);
            }

            // softmax over 200, write att to SMEM
#pragma unroll
            for (int i = 0; i < 8; i++) {
                float m = sc[i][0];
#pragma unroll
                for (int q = 1; q < 6; q++) m = fmaxf(m, sc[i][q]);
                float v6 = (L < 8) ? sc[i][6] : -1e30f;
                m = fmaxf(m, v6);
#pragma unroll
                for (int o = 16; o > 0; o >>= 1)
                    m = fmaxf(m, __shfl_xor_sync(0xFFFFFFFFu, m, o));
                float ex[7], ssum = 0.0f;
#pragma unroll
                for (int q = 0; q < 6; q++) { ex[q] = __expf(sc[i][q] - m); ssum += ex[q]; }
                ex[6] = (L < 8) ? __expf(sc[i][6] - m) : 0.0f;
                ssum += ex[6];
#pragma unroll
                for (int o = 16; o > 0; o >>= 1)
                    ssum += __shfl_xor_sync(0xFFFFFFFFu, ssum, o);
                float inv = 1.0f / ssum;
                int tl = w * 8 + i;
#pragma unroll
                for (int q = 0; q < 6; q++) ATT[tl * 200 + L + 32 * q] = ex[q] * inv;
                if (L < 8) ATT[tl * 200 + 192 + L] = ex[6] * inv;
            }
            __syncwarp();

            // r[t][e] = sum_n att[t][n] * S[n][e]  (e = L, L+32)
#pragma unroll
            for (int i = 0; i < 8; i++) { r0[i] = 0.0f; r1[i] = 0.0f; }
            for (int n = 0; n < NKV; n++) {
                float s0 = S[n * 65 + L];
                float s1 = S[n * 65 + 32 + L];
#pragma unroll
                for (int i = 0; i < 8; i++) {
                    float a = ATT[(w * 8 + i) * 200 + n];
                    r0[i] = fmaf(a, s0, r0[i]);
                    r1[i] = fmaf(a, s1, r1[i]);
                }
            }
        }

        // LSTM cell: z[t][j] = pre_x + H[t] . Whh[j];  h_next = o*tanh(c2) + x
#pragma unroll
        for (int hh = 0; hh < 2; hh++) {
            float z[4][8];
#pragma unroll
            for (int i = 0; i < 4; i++) {
                int grow = trow0 + w * 8 + hh * 4 + i;
#pragma unroll
                for (int q = 0; q < 8; q++)
                    z[i][q] = g_pre_x[grow * 256 + L + 32 * q];
            }
            for (int e = 0; e < 64; e++) {
                float a[4];
#pragma unroll
                for (int i = 0; i < 4; i++) a[i] = H[(w * 8 + hh * 4 + i) * 64 + e];
#pragma unroll
                for (int q = 0; q < 8; q++) {
                    float bv = WH[(L + 32 * q) * 65 + e];
#pragma unroll
                    for (int i = 0; i < 4; i++) z[i][q] = fmaf(a[i], bv, z[i][q]);
                }
            }
            __syncwarp();
#pragma unroll
            for (int i = 0; i < 4; i++) {
                int ii = hh * 4 + i;
                int tl = w * 8 + ii;
                // e = L: gates at q = 0(i),2(f),4(g),6(o)
                float cc = sigf(z[i][2]) * c0[ii] + sigf(z[i][0]) * tanhfast(z[i][4]);
                c0[ii] = cc;
                float h0 = sigf(z[i][6]) * tanhfast(cc) + x0[ii];
                // e = L+32: gates at q = 1,3,5,7
                float cc1 = sigf(z[i][3]) * c1[ii] + sigf(z[i][1]) * tanhfast(z[i][5]);
                c1[ii] = cc1;
                float h1 = sigf(z[i][7]) * tanhfast(cc1) + x1[ii];
                H[tl * 64 + L] = h0;
                H[tl * 64 + 32 + L] = h1;
            }
            __syncwarp();
        }
    }

    // ---- final cosine-similarity softmax ----
    __syncthreads();
    for (int n = tid; n < NKV; n += 256) {
        float ss = 0.0f;
        for (int e = 0; e < 64; e++) { float v = S[n * 65 + e]; ss = fmaf(v, v, ss); }
        SN[n] = sqrtf(ss);
    }
    __syncthreads();

    // num[t][n] = H[t] . S[n]
    float sc[8][7];
#pragma unroll
    for (int i = 0; i < 8; i++)
#pragma unroll
        for (int q = 0; q < 7; q++) sc[i][q] = 0.0f;
    for (int e = 0; e < 64; e++) {
        float a[8];
#pragma unroll
        for (int i = 0; i < 8; i++) a[i] = H[(w * 8 + i) * 64 + e];
#pragma unroll
        for (int q = 0; q < 6; q++) {
            float bv = S[(L + 32 * q) * 65 + e];
#pragma unroll
            for (int i = 0; i < 8; i++) sc[i][q] = fmaf(a[i], bv, sc[i][q]);
        }
        float bv6 = S[n6 * 65 + e];
#pragma unroll
        for (int i = 0; i < 8; i++) sc[i][6] = fmaf(a[i], bv6, sc[i][6]);
    }

#pragma unroll
    for (int i = 0; i < 8; i++) {
        int tl = w * 8 + i;
        // ||H[t]||
        float h0v = H[tl * 64 + L], h1v = H[tl * 64 + 32 + L];
        float p = h0v * h0v + h1v * h1v;
#pragma unroll
        for (int o = 16; o > 0; o >>= 1)
            p += __shfl_xor_sync(0xFFFFFFFFu, p, o);
        float tn = sqrtf(p);

        // sims = num / max(tn*sn, 1e-8)
#pragma unroll
        for (int q = 0; q < 6; q++) {
            float d = fmaxf(tn * SN[L + 32 * q], 1e-8f);
            sc[i][q] = sc[i][q] / d;
        }
        {
            float d6 = fmaxf(tn * SN[n6], 1e-8f);
            sc[i][6] = sc[i][6] / d6;
        }

        // softmax over 200
        float m = sc[i][0];
#pragma unroll
        for (int q = 1; q < 6; q++) m = fmaxf(m, sc[i][q]);
        float v6 = (L < 8) ? sc[i][6] : -1e30f;
        m = fmaxf(m, v6);
#pragma unroll
        for (int o = 16; o > 0; o >>= 1)
            m = fmaxf(m, __shfl_xor_sync(0xFFFFFFFFu, m, o));
        float ex[7], ssum = 0.0f;
#pragma unroll
        for (int q = 0; q < 6; q++) { ex[q] = __expf(sc[i][q] - m); ssum += ex[q]; }
        ex[6] = (L < 8) ? __expf(sc[i][6] - m) : 0.0f;
        ssum += ex[6];
#pragma unroll
        for (int o = 16; o > 0; o >>= 1)
            ssum += __shfl_xor_sync(0xFFFFFFFFu, ssum, o);
        float inv = 1.0f / ssum;

        float* orow = out + (size_t)(trow0 + tl) * 200;
#pragma unroll
        for (int q = 0; q < 6; q++) orow[L + 32 * q] = ex[q] * inv;
        if (L < 8) orow[192 + L] = ex[6] * inv;
    }
}

// ---------------------------------------------------------------------------
extern "C" void kernel_launch(void* const* d_in, const int* in_sizes, int n_in,
                              void* d_out, int out_size)
{
    const int*   sup_tok = (const int*)d_in[0];
    const int*   tgt_tok = (const int*)d_in[1];
    const float* emb     = (const float*)d_in[2];
    const float* f_Wih   = (const float*)d_in[3];
    const float* f_Whh   = (const float*)d_in[4];
    const float* f_bih   = (const float*)d_in[5];
    const float* f_bhh   = (const float*)d_in[6];
    const float* gf_Wih  = (const float*)d_in[7];
    const float* gf_Whh  = (const float*)d_in[8];
    const float* gf_bih  = (const float*)d_in[9];
    const float* gf_bhh  = (const float*)d_in[10];
    const float* gb_Wih  = (const float*)d_in[11];
    const float* gb_Whh  = (const float*)d_in[12];
    const float* gb_bih  = (const float*)d_in[13];
    const float* gb_bhh  = (const float*)d_in[14];
    float* out = (float*)d_out;

    // 1. embedding sums (support + target)
    embed_sum_kernel<<<(SUPROWS + TGTROWS) / 4, 256>>>(sup_tok, tgt_tok, emb);

    float *d_sup_enc, *d_tgt_enc, *d_pre_gf, *d_pre_gb, *d_pre_x;
    cudaGetSymbolAddress((void**)&d_sup_enc, g_sup_enc);
    cudaGetSymbolAddress((void**)&d_tgt_enc, g_tgt_enc);
    cudaGetSymbolAddress((void**)&d_pre_gf, g_pre_gf);
    cudaGetSymbolAddress((void**)&d_pre_gb, g_pre_gb);
    cudaGetSymbolAddress((void**)&d_pre_x, g_pre_x);

    // 2. feedforward gate pre-activations
    gemm_pre_kernel<<<SUPROWS / 64, 256>>>(d_sup_enc, gf_Wih, gf_bih, gf_bhh, d_pre_gf);
    gemm_pre_kernel<<<SUPROWS / 64, 256>>>(d_sup_enc, gb_Wih, gb_bih, gb_bhh, d_pre_gb);
    gemm_pre_kernel<<<TGTROWS / 64, 256>>>(d_tgt_enc, f_Wih, f_bih, f_bhh, d_pre_x);

    // 3. bidirectional LSTM (128 independent chains)
    lstm_kernel<<<BV * 2, 256>>>(gf_Whh, gb_Whh);

    // 4. fused attention loop + final output
    const int smem_bytes = (200 * 65 + 256 * 65 + 64 * 64 + 64 * 200 + 200) * 4;
    cudaFuncSetAttribute(attn_kernel, cudaFuncAttributeMaxDynamicSharedMemorySize,
                         smem_bytes);
    attn_kernel<<<BV * 2, 256, smem_bytes>>>(f_Whh, out);
}

// round 2
// speedup vs baseline: 1.1754x; 1.1754x over previous
#include <cuda_runtime.h>
#include <math.h>

// Problem constants
#define BV 64
#define TV 128
#define LV 40
#define EV 64
#define NKV 200          // N*k
#define G4 256           // 4*E
#define SUPROWS (BV*NKV) // 12800
#define TGTROWS (BV*TV)  // 8192
#define KITERS 5
#define SP 68            // padded row stride for S / WH (16B aligned, conflict-free)

// Scratch (device globals; no allocation allowed)
__device__ float g_sup_enc[SUPROWS*EV];
__device__ float g_tgt_enc[TGTROWS*EV];
__device__ float g_pre_gf[SUPROWS*G4];
__device__ float g_pre_gb[SUPROWS*G4];
__device__ float g_hf[SUPROWS*EV];
__device__ float g_hb[SUPROWS*EV];
__device__ float g_pre_x[TGTROWS*G4];

__device__ __forceinline__ float sigf(float x) { return 1.0f / (1.0f + __expf(-x)); }
__device__ __forceinline__ float tanhfast(float x) {
    float a = fabsf(x);
    float t = __expf(-2.0f * a);
    float r = (1.0f - t) / (1.0f + t);
    return copysignf(r, x);
}

// ---------------------------------------------------------------------------
// Kernel 1: embedding gather-sums. 16 threads per row (float4 per thread),
// 16 rows per 256-thread block.
// ---------------------------------------------------------------------------
__global__ __launch_bounds__(256) void embed_sum_kernel(
    const int* __restrict__ sup_tok,
    const int* __restrict__ tgt_tok,
    const float* __restrict__ emb)
{
    int row = blockIdx.x * 16 + (threadIdx.x >> 4);
    int e = (threadIdx.x & 15) * 4;
    const int* tok;
    float* out;
    if (row < SUPROWS) {
        tok = sup_tok + row * LV;
        out = g_sup_enc + row * EV;
    } else {
        int r2 = row - SUPROWS;
        tok = tgt_tok + r2 * LV;
        out = g_tgt_enc + r2 * EV;
    }
    float ax = 0.f, ay = 0.f, az = 0.f, aw = 0.f;
#pragma unroll 8
    for (int l = 0; l < LV; l++) {
        int t = tok[l];
        float4 v = *(const float4*)&emb[t * EV + e];
        ax += v.x; ay += v.y; az += v.z; aw += v.w;
    }
    float4 o; o.x = ax; o.y = ay; o.z = az; o.w = aw;
    *(float4*)&out[e] = o;
}

// ---------------------------------------------------------------------------
// Kernel 2 (merged): C[M,256] = A[M,64] @ W[256,64]^T + (b1+b2)
// for all three weight sets in one launch. 2 blocks/SM.
// ---------------------------------------------------------------------------
__global__ __launch_bounds__(256, 2) void gemm_all_kernel(
    const float* __restrict__ sup_enc_g, const float* __restrict__ tgt_enc_g,
    const float* __restrict__ gf_W, const float* __restrict__ gf_b1, const float* __restrict__ gf_b2,
    const float* __restrict__ gb_W, const float* __restrict__ gb_b1, const float* __restrict__ gb_b2,
    const float* __restrict__ f_W,  const float* __restrict__ f_b1,  const float* __restrict__ f_b2,
    float* __restrict__ pre_gf, float* __restrict__ pre_gb, float* __restrict__ pre_x)
{
    __shared__ float A_sh[64][64];
    __shared__ float Wt_sh[64][256];
    __shared__ float bias_sh[256];

    int blk = blockIdx.x;
    const float *A, *W, *b1, *b2;
    float* C;
    int row0;
    if (blk < 200)      { A = sup_enc_g; W = gf_W; b1 = gf_b1; b2 = gf_b2; C = pre_gf; row0 = blk * 64; }
    else if (blk < 400) { A = sup_enc_g; W = gb_W; b1 = gb_b1; b2 = gb_b2; C = pre_gb; row0 = (blk - 200) * 64; }
    else                { A = tgt_enc_g; W = f_W;  b1 = f_b1;  b2 = f_b2;  C = pre_x;  row0 = (blk - 400) * 64; }

    int tid = threadIdx.x;
    int tx = tid & 31, ty = tid >> 5;

    for (int idx = tid; idx < 256 * 64; idx += 256) {
        int j = idx >> 6, e = idx & 63;
        Wt_sh[e][j] = W[idx];
    }
    bias_sh[tid] = b1[tid] + b2[tid];
    for (int idx = tid; idx < 64 * 64; idx += 256) {
        A_sh[idx >> 6][idx & 63] = A[row0 * 64 + idx];
    }
    __syncthreads();

    float acc[8][8];
#pragma unroll
    for (int i = 0; i < 8; i++)
#pragma unroll
        for (int q = 0; q < 8; q++) acc[i][q] = 0.0f;

#pragma unroll 4
    for (int e = 0; e < 64; e++) {
        float a[8], bb[8];
#pragma unroll
        for (int i = 0; i < 8; i++) a[i] = A_sh[ty * 8 + i][e];  // broadcast
#pragma unroll
        for (int q = 0; q < 8; q++) bb[q] = Wt_sh[e][tx + 32 * q];
#pragma unroll
        for (int i = 0; i < 8; i++)
#pragma unroll
            for (int q = 0; q < 8; q++) acc[i][q] = fmaf(a[i], bb[q], acc[i][q]);
    }

#pragma unroll
    for (int i = 0; i < 8; i++) {
        int r = row0 + ty * 8 + i;
#pragma unroll
        for (int q = 0; q < 8; q++) {
            int j = tx + 32 * q;
            C[r * 256 + j] = acc[i][q] + bias_sh[j];
        }
    }
}

// ---------------------------------------------------------------------------
// Kernel 3: bidirectional LSTM. One block per (batch, direction).
// Thread (w, L) computes gate row j = (L>>3)*64 + w*8 + (L&7): all 4 gates of
// output e' = w*8+(L&7) live in lanes {x, x+8, x+16, x+24} of the same warp ->
// gate gather via 3 shuffles, no z-smem. h double-buffered: 1 barrier/step.
// 4 accumulators break the 64-FMA RAW chain.
// ---------------------------------------------------------------------------
__global__ __launch_bounds__(256) void lstm_kernel(
    const float* __restrict__ gf_Whh, const float* __restrict__ gb_Whh)
{
    int bx = blockIdx.x;
    int dir = bx & 1, b = bx >> 1;
    int tid = threadIdx.x;
    int L = tid & 31, w = tid >> 5;
    int ep = w * 8 + (L & 7);
    int gate = L >> 3;
    int j = gate * 64 + ep;

    const float* Whh = dir ? gb_Whh : gf_Whh;
    const float* pre = dir ? g_pre_gb : g_pre_gf;
    float* out = dir ? g_hb : g_hf;

    float wr[64];
#pragma unroll
    for (int e = 0; e < 64; e++) wr[e] = Whh[j * 64 + e];

    __shared__ __align__(16) float h_sh[2][64];
    if (tid < 64) h_sh[0][tid] = 0.0f;
    float c = 0.0f;
    __syncthreads();

    int cur = 0;
    for (int s = 0; s < NKV; s++) {
        int srow = dir ? (NKV - 1 - s) : s;
        int row = b * NKV + srow;
        float z = pre[row * 256 + j];
        const float4* h4 = (const float4*)h_sh[cur];
        float a0 = 0.f, a1 = 0.f, a2 = 0.f, a3 = 0.f;
#pragma unroll
        for (int q = 0; q < 16; q++) {
            float4 hv = h4[q];
            a0 = fmaf(hv.x, wr[4 * q + 0], a0);
            a1 = fmaf(hv.y, wr[4 * q + 1], a1);
            a2 = fmaf(hv.z, wr[4 * q + 2], a2);
            a3 = fmaf(hv.w, wr[4 * q + 3], a3);
        }
        z += (a0 + a1) + (a2 + a3);

        float zf = __shfl_down_sync(0xFFFFFFFFu, z, 8);
        float zg = __shfl_down_sync(0xFFFFFFFFu, z, 16);
        float zo = __shfl_down_sync(0xFFFFFFFFu, z, 24);
        if (L < 8) {
            c = sigf(zf) * c + sigf(z) * tanhfast(zg);
            float h = sigf(zo) * tanhfast(c);
            h_sh[cur ^ 1][ep] = h;
            out[row * 64 + ep] = h;
        }
        cur ^= 1;
        __syncthreads();
    }
}

// ---------------------------------------------------------------------------
// Kernel 4: fused K-hop attention + final cosine softmax (float4 SMEM).
// ---------------------------------------------------------------------------
__global__ __launch_bounds__(256) void attn_kernel(
    const float* __restrict__ f_Whh, float* __restrict__ out)
{
    extern __shared__ float sm[];
    float* S   = sm;                      // [200][SP]
    float* WH  = S + 200 * SP;            // [256][SP]
    float* H   = WH + 256 * SP;           // [64][64]
    float* ATT = H + 64 * 64;             // [64][200]
    float* SN  = ATT + 64 * 200;          // [200]

    int tid = threadIdx.x;
    int L = tid & 31, w = tid >> 5;
    int b = blockIdx.x >> 1, half = blockIdx.x & 1;
    int srow0 = b * NKV;
    int trow0 = b * TV + half * 64;

    for (int idx = tid; idx < NKV * 64; idx += 256) {
        int n = idx >> 6, e = idx & 63;
        int gr = (srow0 + n) * 64 + e;
        S[n * SP + e] = g_hf[gr] + g_hb[gr] + g_sup_enc[gr];
    }
    for (int idx = tid; idx < 256 * 64; idx += 256) {
        int j = idx >> 6, e = idx & 63;
        WH[j * SP + e] = f_Whh[idx];
    }
    for (int idx = tid; idx < 64 * 64; idx += 256) H[idx] = 0.0f;

    float x0[8], x1[8], r0[8], r1[8], c0[8], c1[8];
#pragma unroll
    for (int i = 0; i < 8; i++) {
        int grow = trow0 + w * 8 + i;
        x0[i] = g_tgt_enc[grow * 64 + L];
        x1[i] = g_tgt_enc[grow * 64 + 32 + L];
        r0[i] = r1[i] = c0[i] = c1[i] = 0.0f;
    }
    __syncthreads();

    int n6 = 192 + (L & 7);

    for (int iter = 0; iter < KITERS; iter++) {
        // h = h + r
#pragma unroll
        for (int i = 0; i < 8; i++) {
            int tl = w * 8 + i;
            H[tl * 64 + L]      += r0[i];
            H[tl * 64 + 32 + L] += r1[i];
        }
        __syncwarp();

        if (iter < KITERS - 1) {
            float sc[8][7];
#pragma unroll
            for (int i = 0; i < 8; i++)
#pragma unroll
                for (int q = 0; q < 7; q++) sc[i][q] = 0.0f;

            for (int e = 0; e < 64; e += 4) {
                float4 a4[8];
#pragma unroll
                for (int i = 0; i < 8; i++)
                    a4[i] = *(const float4*)&H[(w * 8 + i) * 64 + e];
#pragma unroll
                for (int q = 0; q < 6; q++) {
                    float4 s4 = *(const float4*)&S[(L + 32 * q) * SP + e];
#pragma unroll
                    for (int i = 0; i < 8; i++) {
                        sc[i][q] = fmaf(a4[i].x, s4.x, sc[i][q]);
                        sc[i][q] = fmaf(a4[i].y, s4.y, sc[i][q]);
                        sc[i][q] = fmaf(a4[i].z, s4.z, sc[i][q]);
                        sc[i][q] = fmaf(a4[i].w, s4.w, sc[i][q]);
                    }
                }
                float4 s6 = *(const float4*)&S[n6 * SP + e];
#pragma unroll
                for (int i = 0; i < 8; i++) {
                    sc[i][6] = fmaf(a4[i].x, s6.x, sc[i][6]);
                    sc[i][6] = fmaf(a4[i].y, s6.y, sc[i][6]);
                    sc[i][6] = fmaf(a4[i].z, s6.z, sc[i][6]);
                    sc[i][6] = fmaf(a4[i].w, s6.w, sc[i][6]);
                }
            }

            // softmax over 200, write att to SMEM
#pragma unroll
            for (int i = 0; i < 8; i++) {
                float m = sc[i][0];
#pragma unroll
                for (int q = 1; q < 6; q++) m = fmaxf(m, sc[i][q]);
                float v6 = (L < 8) ? sc[i][6] : -1e30f;
                m = fmaxf(m, v6);
#pragma unroll
                for (int o = 16; o > 0; o >>= 1)
                    m = fmaxf(m, __shfl_xor_sync(0xFFFFFFFFu, m, o));
                float ex[7], ssum = 0.0f;
#pragma unroll
                for (int q = 0; q < 6; q++) { ex[q] = __expf(sc[i][q] - m); ssum += ex[q]; }
                ex[6] = (L < 8) ? __expf(sc[i][6] - m) : 0.0f;
                ssum += ex[6];
#pragma unroll
                for (int o = 16; o > 0; o >>= 1)
                    ssum += __shfl_xor_sync(0xFFFFFFFFu, ssum, o);
                float inv = 1.0f / ssum;
                int tl = w * 8 + i;
#pragma unroll
                for (int q = 0; q < 6; q++) ATT[tl * 200 + L + 32 * q] = ex[q] * inv;
                if (L < 8) ATT[tl * 200 + 192 + L] = ex[6] * inv;
            }
            __syncwarp();

            // r[t][e] = sum_n att[t][n] * S[n][e]
#pragma unroll
            for (int i = 0; i < 8; i++) { r0[i] = 0.0f; r1[i] = 0.0f; }
            for (int n = 0; n < NKV; n += 4) {
                float s0a = S[(n + 0) * SP + L],      s1a = S[(n + 0) * SP + 32 + L];
                float s0b = S[(n + 1) * SP + L],      s1b = S[(n + 1) * SP + 32 + L];
                float s0c = S[(n + 2) * SP + L],      s1c = S[(n + 2) * SP + 32 + L];
                float s0d = S[(n + 3) * SP + L],      s1d = S[(n + 3) * SP + 32 + L];
#pragma unroll
                for (int i = 0; i < 8; i++) {
                    float4 a = *(const float4*)&ATT[(w * 8 + i) * 200 + n];
                    r0[i] = fmaf(a.x, s0a, r0[i]); r1[i] = fmaf(a.x, s1a, r1[i]);
                    r0[i] = fmaf(a.y, s0b, r0[i]); r1[i] = fmaf(a.y, s1b, r1[i]);
                    r0[i] = fmaf(a.z, s0c, r0[i]); r1[i] = fmaf(a.z, s1c, r1[i]);
                    r0[i] = fmaf(a.w, s0d, r0[i]); r1[i] = fmaf(a.w, s1d, r1[i]);
                }
            }
        }

        // LSTM cell
#pragma unroll
        for (int hh = 0; hh < 2; hh++) {
            float z[4][8];
#pragma unroll
            for (int i = 0; i < 4; i++) {
                int grow = trow0 + w * 8 + hh * 4 + i;
#pragma unroll
                for (int q = 0; q < 8; q++)
                    z[i][q] = g_pre_x[grow * 256 + L + 32 * q];
            }
            for (int e = 0; e < 64; e += 4) {
                float4 a4[4];
#pragma unroll
                for (int i = 0; i < 4; i++)
                    a4[i] = *(const float4*)&H[(w * 8 + hh * 4 + i) * 64 + e];
#pragma unroll
                for (int q = 0; q < 8; q++) {
                    float4 w4 = *(const float4*)&WH[(L + 32 * q) * SP + e];
#pragma unroll
                    for (int i = 0; i < 4; i++) {
                        z[i][q] = fmaf(a4[i].x, w4.x, z[i][q]);
                        z[i][q] = fmaf(a4[i].y, w4.y, z[i][q]);
                        z[i][q] = fmaf(a4[i].z, w4.z, z[i][q]);
                        z[i][q] = fmaf(a4[i].w, w4.w, z[i][q]);
                    }
                }
            }
            __syncwarp();
#pragma unroll
            for (int i = 0; i < 4; i++) {
                int ii = hh * 4 + i;
                int tl = w * 8 + ii;
                float cc = sigf(z[i][2]) * c0[ii] + sigf(z[i][0]) * tanhfast(z[i][4]);
                c0[ii] = cc;
                float h0 = sigf(z[i][6]) * tanhfast(cc) + x0[ii];
                float cc1 = sigf(z[i][3]) * c1[ii] + sigf(z[i][1]) * tanhfast(z[i][5]);
                c1[ii] = cc1;
                float h1 = sigf(z[i][7]) * tanhfast(cc1) + x1[ii];
                H[tl * 64 + L] = h0;
                H[tl * 64 + 32 + L] = h1;
            }
            __syncwarp();
        }
    }

    // ---- final cosine-similarity softmax ----
    __syncthreads();
    for (int n = tid; n < NKV; n += 256) {
        float ss = 0.0f;
        for (int e = 0; e < 64; e += 4) {
            float4 v = *(const float4*)&S[n * SP + e];
            ss = fmaf(v.x, v.x, ss); ss = fmaf(v.y, v.y, ss);
            ss = fmaf(v.z, v.z, ss); ss = fmaf(v.w, v.w, ss);
        }
        SN[n] = sqrtf(ss);
    }
    __syncthreads();

    float sc[8][7];
#pragma unroll
    for (int i = 0; i < 8; i++)
#pragma unroll
        for (int q = 0; q < 7; q++) sc[i][q] = 0.0f;
    for (int e = 0; e < 64; e += 4) {
        float4 a4[8];
#pragma unroll
        for (int i = 0; i < 8; i++)
            a4[i] = *(const float4*)&H[(w * 8 + i) * 64 + e];
#pragma unroll
        for (int q = 0; q < 6; q++) {
            float4 s4 = *(const float4*)&S[(L + 32 * q) * SP + e];
#pragma unroll
            for (int i = 0; i < 8; i++) {
                sc[i][q] = fmaf(a4[i].x, s4.x, sc[i][q]);
                sc[i][q] = fmaf(a4[i].y, s4.y, sc[i][q]);
                sc[i][q] = fmaf(a4[i].z, s4.z, sc[i][q]);
                sc[i][q] = fmaf(a4[i].w, s4.w, sc[i][q]);
            }
        }
        float4 s6 = *(const float4*)&S[n6 * SP + e];
#pragma unroll
        for (int i = 0; i < 8; i++) {
            sc[i][6] = fmaf(a4[i].x, s6.x, sc[i][6]);
            sc[i][6] = fmaf(a4[i].y, s6.y, sc[i][6]);
            sc[i][6] = fmaf(a4[i].z, s6.z, sc[i][6]);
            sc[i][6] = fmaf(a4[i].w, s6.w, sc[i][6]);
        }
    }

#pragma unroll
    for (int i = 0; i < 8; i++) {
        int tl = w * 8 + i;
        float h0v = H[tl * 64 + L], h1v = H[tl * 64 + 32 + L];
        float p = h0v * h0v + h1v * h1v;
#pragma unroll
        for (int o = 16; o > 0; o >>= 1)
            p += __shfl_xor_sync(0xFFFFFFFFu, p, o);
        float tn = sqrtf(p);

#pragma unroll
        for (int q = 0; q < 6; q++) {
            float d = fmaxf(tn * SN[L + 32 * q], 1e-8f);
            sc[i][q] = sc[i][q] / d;
        }
        {
            float d6 = fmaxf(tn * SN[n6], 1e-8f);
            sc[i][6] = sc[i][6] / d6;
        }

        float m = sc[i][0];
#pragma unroll
        for (int q = 1; q < 6; q++) m = fmaxf(m, sc[i][q]);
        float v6 = (L < 8) ? sc[i][6] : -1e30f;
        m = fmaxf(m, v6);
#pragma unroll
        for (int o = 16; o > 0; o >>= 1)
            m = fmaxf(m, __shfl_xor_sync(0xFFFFFFFFu, m, o));
        float ex[7], ssum = 0.0f;
#pragma unroll
        for (int q = 0; q < 6; q++) { ex[q] = __expf(sc[i][q] - m); ssum += ex[q]; }
        ex[6] = (L < 8) ? __expf(sc[i][6] - m) : 0.0f;
        ssum += ex[6];
#pragma unroll
        for (int o = 16; o > 0; o >>= 1)
            ssum += __shfl_xor_sync(0xFFFFFFFFu, ssum, o);
        float inv = 1.0f / ssum;

        float* orow = out + (size_t)(trow0 + tl) * 200;
#pragma unroll
        for (int q = 0; q < 6; q++) orow[L + 32 * q] = ex[q] * inv;
        if (L < 8) orow[192 + L] = ex[6] * inv;
    }
}

// ---------------------------------------------------------------------------
extern "C" void kernel_launch(void* const* d_in, const int* in_sizes, int n_in,
                              void* d_out, int out_size)
{
    const int*   sup_tok = (const int*)d_in[0];
    const int*   tgt_tok = (const int*)d_in[1];
    const float* emb     = (const float*)d_in[2];
    const float* f_Wih   = (const float*)d_in[3];
    const float* f_Whh   = (const float*)d_in[4];
    const float* f_bih   = (const float*)d_in[5];
    const float* f_bhh   = (const float*)d_in[6];
    const float* gf_Wih  = (const float*)d_in[7];
    const float* gf_Whh  = (const float*)d_in[8];
    const float* gf_bih  = (const float*)d_in[9];
    const float* gf_bhh  = (const float*)d_in[10];
    const float* gb_Wih  = (const float*)d_in[11];
    const float* gb_Whh  = (const float*)d_in[12];
    const float* gb_bih  = (const float*)d_in[13];
    const float* gb_bhh  = (const float*)d_in[14];
    float* out = (float*)d_out;

    float *d_sup_enc, *d_tgt_enc, *d_pre_gf, *d_pre_gb, *d_pre_x;
    cudaGetSymbolAddress((void**)&d_sup_enc, g_sup_enc);
    cudaGetSymbolAddress((void**)&d_tgt_enc, g_tgt_enc);
    cudaGetSymbolAddress((void**)&d_pre_gf, g_pre_gf);
    cudaGetSymbolAddress((void**)&d_pre_gb, g_pre_gb);
    cudaGetSymbolAddress((void**)&d_pre_x, g_pre_x);

    // 1. embedding sums
    embed_sum_kernel<<<(SUPROWS + TGTROWS) / 16, 256>>>(sup_tok, tgt_tok, emb);

    // 2. all three gate-preactivation GEMMs in one launch
    gemm_all_kernel<<<528, 256>>>(d_sup_enc, d_tgt_enc,
                                  gf_Wih, gf_bih, gf_bhh,
                                  gb_Wih, gb_bih, gb_bhh,
                                  f_Wih, f_bih, f_bhh,
                                  d_pre_gf, d_pre_gb, d_pre_x);

    // 3. bidirectional LSTM
    lstm_kernel<<<BV * 2, 256>>>(gf_Whh, gb_Whh);

    // 4. fused attention loop + final output
    const int smem_bytes = (200 * SP + 256 * SP + 64 * 64 + 64 * 200 + 200) * 4;
    cudaFuncSetAttribute(attn_kernel, cudaFuncAttributeMaxDynamicSharedMemorySize,
                         smem_bytes);
    attn_kernel<<<BV * 2, 256, smem_bytes>>>(f_Whh, out);
}